// round 1
// baseline (speedup 1.0000x reference)
#include <cuda_runtime.h>

// PZCell: real biquad y[t] = b0 x[t] + b1 x[t-1] + b2 x[t-2] - a1 y[t-1] - a2 y[t-2]
// b = Re(gain * zero_coeffs), a = Re(pole_coeffs); den == 1 by construction.
// Layout: 128 blocks x 64 threads. Block owns 32 rows. Warp0 = compute (1 row/lane),
// warp1 = IO (cp.async loads + coalesced float4 stores), 4-buffer SMEM ring.

namespace {
constexpr int T_LEN  = 2048;
constexpr int B_ROWS = 4096;
constexpr int BROWS  = 32;            // rows per block
constexpr int CHUNK  = 128;           // time steps per chunk
constexpr int PADW   = 132;           // padded row pitch (floats): 33 x 16B granules -> conflict-free
constexpr int NBUF   = 4;
constexpr int NC     = T_LEN / CHUNK; // 16
constexpr int SMEM_BYTES = NBUF * BROWS * PADW * (int)sizeof(float); // 67584
}

__device__ __forceinline__ void cp_async16(float* smem_dst, const float* gmem_src) {
    unsigned s = (unsigned)__cvta_generic_to_shared(smem_dst);
    asm volatile("cp.async.cg.shared.global [%0], [%1], 16;" :: "r"(s), "l"(gmem_src));
}
__device__ __forceinline__ void cp_commit() { asm volatile("cp.async.commit_group;"); }
__device__ __forceinline__ void cp_wait2()  { asm volatile("cp.async.wait_group 2;" ::: "memory"); }

extern "C" __global__ void __launch_bounds__(64, 1)
pz_kernel(const float* __restrict__ x, const float* __restrict__ gain_ri,
          const float* __restrict__ poles_ri, const float* __restrict__ zeros_ri,
          float* __restrict__ out)
{
    extern __shared__ float sbuf[];
    const int  tid  = threadIdx.x;
    const int  lane = tid & 31;
    const int  wid  = tid >> 5;
    const long row0 = (long)blockIdx.x * BROWS;

    const float* xb = x   + row0 * T_LEN;
    float*       yb = out + row0 * T_LEN;

    // ---- prolog: IO warp preloads chunks 0,1,2 (3 commit groups) ----
    if (wid == 1) {
        #pragma unroll
        for (int c = 0; c < 3; ++c) {
            float* sb = sbuf + c * (BROWS * PADW);
            const float* g = xb + c * CHUNK + lane * 4;
            #pragma unroll 4
            for (int r = 0; r < BROWS; ++r)
                cp_async16(sb + r * PADW + lane * 4, g + (long)r * T_LEN);
            cp_commit();
        }
        cp_wait2();   // chunk 0 resident
    }
    __syncthreads();

    // ---- coefficients (every thread; trivial) ----
    const float gr = gain_ri[0], gi = gain_ri[1];
    const float pr0 = poles_ri[0], pi0 = poles_ri[1];
    const float pr1 = poles_ri[2], pi1 = poles_ri[3];
    const float zr0 = zeros_ri[0], zi0 = zeros_ri[1];
    const float zr1 = zeros_ri[2], zi1 = zeros_ri[3];
    const float a1 = -(pr0 + pr1);
    const float a2 = pr0 * pr1 - pi0 * pi1;
    const float zc1r = -(zr0 + zr1), zc1i = -(zi0 + zi1);
    const float zc2r = zr0 * zr1 - zi0 * zi1;
    const float zc2i = zr0 * zi1 + zi0 * zr1;
    const float b0 = gr;
    const float b1 = gr * zc1r - gi * zc1i;
    const float b2 = gr * zc2r - gi * zc2i;
    // 2-step jump coefficients: y[t+1] = (u1 - a1 u0) + (a1^2 - a2) p + (a1 a2) q
    const float A2 = a1 * a1 - a2;
    const float Bc = a1 * a2;

    float x1 = 0.f, x2 = 0.f;   // x[t-1], x[t-2]
    float p  = 0.f, q  = 0.f;   // y[t-1], y[t-2]

    for (int c = 0; c < NC; ++c) {
        if (wid == 0) {
            // compute chunk c in place (x tile -> y tile), one row per lane
            float* sb = sbuf + (c & 3) * (BROWS * PADW) + lane * PADW;
            #pragma unroll 8
            for (int g = 0; g < CHUNK / 4; ++g) {
                float4 xv = *reinterpret_cast<float4*>(sb + 4 * g);
                float u0 = fmaf(b0, xv.x, fmaf(b1, x1,   b2 * x2));
                float u1 = fmaf(b0, xv.y, fmaf(b1, xv.x, b2 * x1));
                float u2 = fmaf(b0, xv.z, fmaf(b1, xv.y, b2 * xv.x));
                float u3 = fmaf(b0, xv.w, fmaf(b1, xv.z, b2 * xv.y));
                x2 = xv.z; x1 = xv.w;
                float w1 = fmaf(-a1, u0, u1);
                float w3 = fmaf(-a1, u2, u3);
                float yA = fmaf(-a1, p,  fmaf(-a2, q,  u0));
                float yB = fmaf( A2, p,  fmaf( Bc, q,  w1));
                float yC = fmaf(-a1, yB, fmaf(-a2, yA, u2));
                float yD = fmaf( A2, yB, fmaf( Bc, yA, w3));
                p = yD; q = yC;
                *reinterpret_cast<float4*>(sb + 4 * g) = make_float4(yA, yB, yC, yD);
            }
        } else {
            // store y of chunk c-1 (coalesced), then prefetch chunk c+3 into same ring slot
            if (c > 0) {
                float* sb = sbuf + ((c - 1) & 3) * (BROWS * PADW);
                float* gy = yb + (c - 1) * CHUNK + lane * 4;
                #pragma unroll 4
                for (int r = 0; r < BROWS; ++r) {
                    float4 v = *reinterpret_cast<float4*>(sb + r * PADW + lane * 4);
                    *reinterpret_cast<float4*>(gy + (long)r * T_LEN) = v;
                }
            }
            if (c + 3 < NC) {
                float* sb = sbuf + ((c + 3) & 3) * (BROWS * PADW);
                const float* g = xb + (c + 3) * CHUNK + lane * 4;
                #pragma unroll 4
                for (int r = 0; r < BROWS; ++r)
                    cp_async16(sb + r * PADW + lane * 4, g + (long)r * T_LEN);
            }
            cp_commit();          // always commit (possibly empty) -> wait_group count invariant
            cp_wait2();           // guarantees chunk c+1 resident before next iteration
        }
        __syncthreads();
    }

    // epilogue: store last chunk
    if (wid == 1) {
        float* sb = sbuf + ((NC - 1) & 3) * (BROWS * PADW);
        float* gy = yb + (NC - 1) * CHUNK + lane * 4;
        #pragma unroll 4
        for (int r = 0; r < BROWS; ++r) {
            float4 v = *reinterpret_cast<float4*>(sb + r * PADW + lane * 4);
            *reinterpret_cast<float4*>(gy + (long)r * T_LEN) = v;
        }
    }
}

extern "C" void kernel_launch(void* const* d_in, const int* in_sizes, int n_in,
                              void* d_out, int out_size) {
    (void)in_sizes; (void)n_in; (void)out_size;
    const float* x        = (const float*)d_in[0];
    const float* gain_ri  = (const float*)d_in[1];
    const float* poles_ri = (const float*)d_in[2];
    const float* zeros_ri = (const float*)d_in[3];
    float* out = (float*)d_out;

    cudaFuncSetAttribute(pz_kernel, cudaFuncAttributeMaxDynamicSharedMemorySize, SMEM_BYTES);
    pz_kernel<<<B_ROWS / BROWS, 64, SMEM_BYTES>>>(x, gain_ri, poles_ri, zeros_ri, out);
}